// round 14
// baseline (speedup 1.0000x reference)
#include <cuda_runtime.h>
#include <cuda_fp16.h>

// Problem constants (fixed shapes)
#define NU 100000
#define NI 50000
#define NN 150000        // NU + NI
#define D  64
#define DE 16
#define NE 1500000
#define NP 14
#define EPS 1e-5f

#define NN2 (2 * NN)     // row counters for both layers
#define NE2 (2 * NE)     // CSR slots for both layers
#define SCAN_BLK 1024
#define NB2 ((NN2 + SCAN_BLK - 1) / SCAN_BLK)  // 293
#define ROWB ((NN + 7) / 8)                     // 18750 (8 warps/block)
#define HISTB ((NE2 / 4 + 255) / 256)           // 2930

// -------- scratch (device globals; no allocation allowed) --------
__device__ __half g_yh0[NN * D];    // LN features layer 0 (fp16)
__device__ __half g_yh1[NN * D];    // LN features layer 1 (fp16)
__device__ __half g_eh [NN * DE];   // eigs fp16
__device__ float  g_x0 [NN * D];    // layer-0 output (fp32 for final avg)
__device__ int    g_cnt[NN2];       // row degrees (both layers)
__device__ int    g_rs [NN2];       // block-local scan; bumped to local END by score
__device__ int2   g_csr[NE2];       // CSR: (c | pt<<20, e0 bits) — 8 B/slot
__device__ float  g_pwx[2 * NP];    // clip(exp(path_w),5) per layer
__device__ int    g_part[512];      // per-scan-block offsets (final, exclusive)
__device__ int    g_scan_ctr;

// ---------------------------------------------------------------
// K0: zero counters, reset scan counter, eigs -> fp16, pwx table.
// ---------------------------------------------------------------
__global__ void prep_kernel(const float* __restrict__ eigs,
                            const float* __restrict__ pw)
{
    int i = blockIdx.x * blockDim.x + threadIdx.x;
    if (i == 0) g_scan_ctr = 0;
    if (i < 2 * NP) g_pwx[i] = fminf(__expf(__ldg(pw + i)), 5.0f);
    if (i < NN2) g_cnt[i] = 0;
    if (i < NN * DE / 2) {
        float2 v = ((const float2*)eigs)[i];
        ((__half2*)g_eh)[i] = __floats2half2_rn(v.x, v.y);
    }
}

// ---------------------------------------------------------------
// K1: fused LN(layer 0) + histogram(both layers).
// g_cnt pre-zeroed in K0 (no in-kernel zeroing — R3's race).
// ---------------------------------------------------------------
__global__ void ln_hist_kernel(const float* __restrict__ ue,
                               const float* __restrict__ ie,
                               const int*   __restrict__ idx)
{
    if (blockIdx.x < ROWB) {
        int row = blockIdx.x * 8 + (threadIdx.x >> 5);
        if (row >= NN) return;
        int lane = threadIdx.x & 31;

        const float* p = (row < NU) ? (ue + (size_t)row * D)
                                    : (ie + (size_t)(row - NU) * D);
        float2 v = ((const float2*)p)[lane];

        float s = v.x + v.y;
        #pragma unroll
        for (int o = 16; o; o >>= 1) s += __shfl_xor_sync(0xffffffffu, s, o);
        float mu = s * (1.0f / D);

        float dx = v.x - mu, dy = v.y - mu;
        float vs = dx * dx + dy * dy;
        #pragma unroll
        for (int o = 16; o; o >>= 1) vs += __shfl_xor_sync(0xffffffffu, vs, o);
        float inv = rsqrtf(vs * (1.0f / D) + EPS);

        ((__half2*)(g_yh0 + (size_t)row * D))[lane] =
            __floats2half2_rn(dx * inv, dy * inv);
    } else {
        int e4 = (blockIdx.x - ROWB) * blockDim.x + threadIdx.x;
        if (e4 < NE2 / 4) {
            int layer = (e4 >= NE / 4);
            const int* rows = idx + (size_t)layer * 2 * NE;
            int4 r4 = ((const int4*)rows)[e4 - layer * (NE / 4)];
            int base = layer * NN;
            atomicAdd(&g_cnt[base + r4.x], 1);
            atomicAdd(&g_cnt[base + r4.y], 1);
            atomicAdd(&g_cnt[base + r4.z], 1);
            atomicAdd(&g_cnt[base + r4.w], 1);
        }
    }
}

// ---------------------------------------------------------------
// K2: block-local exclusive scan of g_cnt -> g_rs; last finishing
// block scans the block totals -> g_part (final offsets).
// ---------------------------------------------------------------
__device__ __forceinline__ int warp_incl_scan(int x, int lane)
{
    #pragma unroll
    for (int o = 1; o < 32; o <<= 1) {
        int t = __shfl_up_sync(0xffffffffu, x, o);
        if (lane >= o) x += t;
    }
    return x;
}

__global__ void scan_kernel()
{
    __shared__ int warpsum[32];
    __shared__ int s_total;
    __shared__ int s_isLast;

    int lane = threadIdx.x & 31;
    int wid  = threadIdx.x >> 5;
    int i = blockIdx.x * SCAN_BLK + threadIdx.x;
    int v = (i < NN2) ? g_cnt[i] : 0;

    int inc = warp_incl_scan(v, lane);
    if (lane == 31) warpsum[wid] = inc;
    __syncthreads();
    if (wid == 0) {
        int s  = warpsum[lane];
        int si = warp_incl_scan(s, lane);
        warpsum[lane] = si - s;
        if (lane == 31) s_total = si;
    }
    __syncthreads();
    int excl = inc - v + warpsum[wid];
    if (i < NN2) g_rs[i] = excl;                 // block-local exclusive scan

    if (threadIdx.x == 0) {
        g_part[blockIdx.x] = s_total;
        __threadfence();
        s_isLast = (atomicAdd(&g_scan_ctr, 1) == (int)gridDim.x - 1);
    }
    __syncthreads();

    if (s_isLast) {
        int pv = (threadIdx.x < NB2) ? g_part[threadIdx.x] : 0;
        int inc2 = warp_incl_scan(pv, lane);
        __syncthreads();
        if (lane == 31) warpsum[wid] = inc2;
        __syncthreads();
        if (wid == 0) {
            int s  = warpsum[lane];
            int si = warp_incl_scan(s, lane);
            warpsum[lane] = si - s;
        }
        __syncthreads();
        int excl2 = inc2 - pv + warpsum[wid];
        if (threadIdx.x < NB2) g_part[threadIdx.x] = excl2;
    }
}

// ---------------------------------------------------------------
// K3: scores in EDGE order, 8 lanes per FOUR edges + fused CSR
// scatter. One LDG.128 covers a full 128B feature row (8 lanes x
// 16B) -> minimum L1 wavefronts (2/edge for features). Thread count
// identical to the 4-lane/2-edge shape; epilogue spreads the 4
// edges over lanes 0..3. HFMA2 feature dots; fp32 eigs dots.
// ---------------------------------------------------------------
__device__ __forceinline__ float dot16h(uint4 a, uint4 b)
{
    const __half2* ah = (const __half2*)&a;
    const __half2* bh = (const __half2*)&b;
    __half2 acc = __floats2half2_rn(0.f, 0.f);
    acc = __hfma2(ah[0], bh[0], acc);
    acc = __hfma2(ah[1], bh[1], acc);
    acc = __hfma2(ah[2], bh[2], acc);
    acc = __hfma2(ah[3], bh[3], acc);
    float2 f = __half22float2(acc);
    return f.x + f.y;
}

__global__ void score_kernel(const __half* __restrict__ yh,
                             const int*   __restrict__ rows,
                             const int*   __restrict__ cols,
                             const int*   __restrict__ pt,
                             const float* __restrict__ lam,
                             int rowBase)
{
    int t = blockIdx.x * blockDim.x + threadIdx.x;
    int grp = t >> 3;                  // edge-quad index
    if (grp >= NE / 4) return;
    int q = t & 7;

    int4 rr = __ldg((const int4*)rows + grp);   // rows[4g .. 4g+3]
    int4 cc = __ldg((const int4*)cols + grp);

    // 8 independent full-line loads (one uint4 per lane per row)
    uint4 aA = __ldg((const uint4*)(yh + (size_t)rr.x * D) + q);
    uint4 bA = __ldg((const uint4*)(yh + (size_t)cc.x * D) + q);
    uint4 aB = __ldg((const uint4*)(yh + (size_t)rr.y * D) + q);
    uint4 bB = __ldg((const uint4*)(yh + (size_t)cc.y * D) + q);
    uint4 aC = __ldg((const uint4*)(yh + (size_t)rr.z * D) + q);
    uint4 bC = __ldg((const uint4*)(yh + (size_t)cc.z * D) + q);
    uint4 aD = __ldg((const uint4*)(yh + (size_t)rr.w * D) + q);
    uint4 bD = __ldg((const uint4*)(yh + (size_t)cc.w * D) + q);

    // eigs fp16: 16 halves = 32B/row; 8 lanes x half2 covers it
    __half2 euA = __ldg((const __half2*)(g_eh + (size_t)rr.x * DE) + q);
    __half2 evA = __ldg((const __half2*)(g_eh + (size_t)cc.x * DE) + q);
    __half2 euB = __ldg((const __half2*)(g_eh + (size_t)rr.y * DE) + q);
    __half2 evB = __ldg((const __half2*)(g_eh + (size_t)cc.y * DE) + q);
    __half2 euC = __ldg((const __half2*)(g_eh + (size_t)rr.z * DE) + q);
    __half2 evC = __ldg((const __half2*)(g_eh + (size_t)cc.z * DE) + q);
    __half2 euD = __ldg((const __half2*)(g_eh + (size_t)rr.w * DE) + q);
    __half2 evD = __ldg((const __half2*)(g_eh + (size_t)cc.w * DE) + q);

    float dpA = dot16h(aA, bA);
    float dpB = dot16h(aB, bB);
    float dpC = dot16h(aC, bC);
    float dpD = dot16h(aD, bD);

    float2 u, v;
    u = __half22float2(euA); v = __half22float2(evA);
    float ysA = u.x * v.x + u.y * v.y;
    u = __half22float2(euB); v = __half22float2(evB);
    float ysB = u.x * v.x + u.y * v.y;
    u = __half22float2(euC); v = __half22float2(evC);
    float ysC = u.x * v.x + u.y * v.y;
    u = __half22float2(euD); v = __half22float2(evD);
    float ysD = u.x * v.x + u.y * v.y;

    float elam = __expf(__ldg(lam));
    float pA = dpA * 0.125f + elam * ysA;
    float pB = dpB * 0.125f + elam * ysB;
    float pC = dpC * 0.125f + elam * ysC;
    float pD = dpD * 0.125f + elam * ysD;
    #pragma unroll
    for (int o = 1; o <= 4; o <<= 1) {
        pA += __shfl_xor_sync(0xffffffffu, pA, o);
        pB += __shfl_xor_sync(0xffffffffu, pB, o);
        pC += __shfl_xor_sync(0xffffffffu, pC, o);
        pD += __shfl_xor_sync(0xffffffffu, pD, o);
    }

    // epilogue: lanes 0..3 handle edges A..D
    if (q < 4) {
        int4 pp = __ldg((const int4*)pt + grp);
        int   r, c, ptv; float p;
        if      (q == 0) { r = rr.x; c = cc.x; ptv = pp.x; p = pA; }
        else if (q == 1) { r = rr.y; c = cc.y; ptv = pp.y; p = pB; }
        else if (q == 2) { r = rr.z; c = cc.z; ptv = pp.z; p = pC; }
        else             { r = rr.w; c = cc.w; ptv = pp.w; p = pD; }
        float v0 = fminf(__expf(p), 5.0f);                     // clip(exp,-5,5)
        int ridx = rowBase + r;
        int pos = atomicAdd(&g_rs[ridx], 1) + __ldg(&g_part[ridx >> 10]);
        g_csr[pos] = make_int2(c | (ptv << 20), __float_as_int(v0));
    }
}

// ---------------------------------------------------------------
// K4: SpMM warp/row. CSR slots are 8B; main loop loads TWO slots per
// int4 (16B) instruction (peel one if row start is odd). e1 comes
// from the 14-entry pwx table (L1-resident broadcast). fp32 math.
//   MODE 0: epilogue LN -> yh1 fp16 + x0 fp32.
//   MODE 1: epilogue out = (emb + x0 + x)/3.
// ---------------------------------------------------------------
template<int MODE>
__global__ void spmm_kernel(const __half* __restrict__ yh,
                            int rowBase,
                            const float* __restrict__ pwx,   // &g_pwx[l*NP]
                            const float* __restrict__ ue,
                            const float* __restrict__ ie,
                            float* __restrict__ out)
{
    int row = blockIdx.x * 8 + (threadIdx.x >> 5);
    if (row >= NN) return;
    int lane = threadIdx.x & 31;

    int ridx = rowBase + row;
    int n  = g_cnt[ridx];
    // g_rs holds block-local END (bumped by score); add part, sub n.
    int st  = g_rs[ridx] + __ldg(&g_part[ridx >> 10]) - n;
    int end = st + n;

    float s0 = 0.f, s1 = 0.f;
    float a0x = 0.f, a0y = 0.f, a1x = 0.f, a1y = 0.f;

    int i = st;
    if ((i & 1) && i < end) {                    // peel to even index
        int2 cw = __ldg(&g_csr[i]);
        int   c   = cw.x & 0xFFFFF;
        float e1  = __ldg(pwx + (cw.x >> 20));
        float e0  = __int_as_float(cw.y);
        float2 v  = __half22float2(((const __half2*)(yh + (size_t)c * D))[lane]);
        a0x += e0 * v.x; a0y += e0 * v.y;
        a1x += e1 * v.x; a1y += e1 * v.y;
        s0 += e0; s1 += e1;
        i++;
    }
    for (; i + 2 <= end; i += 2) {
        int4 two = __ldg((const int4*)g_csr + (i >> 1));   // slots i, i+1
        int   cA  = two.x & 0xFFFFF;
        int   cB  = two.z & 0xFFFFF;
        float e1A = __ldg(pwx + (two.x >> 20));
        float e1B = __ldg(pwx + (two.z >> 20));
        float e0A = __int_as_float(two.y);
        float e0B = __int_as_float(two.w);
        __half2 hA = ((const __half2*)(yh + (size_t)cA * D))[lane];
        __half2 hB = ((const __half2*)(yh + (size_t)cB * D))[lane];
        float2 vA = __half22float2(hA);
        float2 vB = __half22float2(hB);
        a0x += e0A * vA.x + e0B * vB.x;
        a0y += e0A * vA.y + e0B * vB.y;
        a1x += e1A * vA.x + e1B * vB.x;
        a1y += e1A * vA.y + e1B * vB.y;
        s0 += e0A + e0B;
        s1 += e1A + e1B;
    }
    if (i < end) {
        int2 cw = __ldg(&g_csr[i]);
        int   c   = cw.x & 0xFFFFF;
        float e1  = __ldg(pwx + (cw.x >> 20));
        float e0  = __int_as_float(cw.y);
        float2 v  = __half22float2(((const __half2*)(yh + (size_t)c * D))[lane]);
        a0x += e0 * v.x; a0y += e0 * v.y;
        a1x += e1 * v.x; a1y += e1 * v.y;
        s0 += e0; s1 += e1;
    }

    float i0 = 0.5f / ((s0 == 0.f) ? 1.f : s0);
    float i1 = 0.5f / ((s1 == 0.f) ? 1.f : s1);
    float ax = a0x * i0 + a1x * i1;
    float ay = a0y * i0 + a1y * i1;

    if (MODE == 0) {
        // fused LayerNorm -> yh1 (fp16), plus x0 (fp32)
        float s = ax + ay;
        #pragma unroll
        for (int o = 16; o; o >>= 1) s += __shfl_xor_sync(0xffffffffu, s, o);
        float mu = s * (1.0f / D);
        float dx = ax - mu, dy = ay - mu;
        float vs = dx * dx + dy * dy;
        #pragma unroll
        for (int o = 16; o; o >>= 1) vs += __shfl_xor_sync(0xffffffffu, vs, o);
        float inv = rsqrtf(vs * (1.0f / D) + EPS);

        ((float2*)(g_x0 + (size_t)row * D))[lane] = make_float2(ax, ay);
        ((__half2*)(g_yh1 + (size_t)row * D))[lane] =
            __floats2half2_rn(dx * inv, dy * inv);
    } else {
        const float* emb = (row < NU) ? (ue + (size_t)row * D)
                                      : (ie + (size_t)(row - NU) * D);
        float2 e = ((const float2*)emb)[lane];
        float2 x = ((const float2*)(g_x0 + (size_t)row * D))[lane];
        const float t = 1.0f / 3.0f;
        ((float2*)(out + (size_t)row * D))[lane] =
            make_float2((e.x + x.x + ax) * t, (e.y + x.y + ay) * t);
    }
}

extern "C" void kernel_launch(void* const* d_in, const int* in_sizes, int n_in,
                              void* d_out, int out_size)
{
    const float* ue   = (const float*)d_in[0];  // [NU, D]
    const float* ie   = (const float*)d_in[1];  // [NI, D]
    const float* eigs = (const float*)d_in[2];  // [NN, DE]
    const float* lam  = (const float*)d_in[3];  // [2]
    const float* pw   = (const float*)d_in[4];  // [2, NP]
    const int*   idx  = (const int*)  d_in[5];  // [2, 2, NE]
    const int*   pt   = (const int*)  d_in[6];  // [2, NE]
    float* out = (float*)d_out;

    __half* yh0 = nullptr; __half* yh1 = nullptr; float* pwx = nullptr;
    cudaGetSymbolAddress((void**)&yh0, g_yh0);
    cudaGetSymbolAddress((void**)&yh1, g_yh1);
    cudaGetSymbolAddress((void**)&pwx, g_pwx);

    int prepT = NN * DE / 2;                     // 1.2M threads (covers NN2)
    prep_kernel   <<<(prepT + 255) / 256, 256>>>(eigs, pw);
    ln_hist_kernel<<<ROWB + HISTB, 256>>>(ue, ie, idx);
    scan_kernel   <<<NB2, SCAN_BLK>>>();

    int scoreB = ((NE / 4) * 8 + 255) / 256;
    // layer 0
    score_kernel  <<<scoreB, 256>>>(yh0, idx, idx + NE, pt, lam, 0);
    spmm_kernel<0><<<ROWB, 256>>>(yh0, 0, pwx, nullptr, nullptr, nullptr);
    // layer 1
    score_kernel  <<<scoreB, 256>>>(yh1, idx + 2 * NE, idx + 3 * NE,
                                    pt + NE, lam + 1, NN);
    spmm_kernel<1><<<ROWB, 256>>>(yh1, NN, pwx + NP, ue, ie, out);
}

// round 15
// speedup vs baseline: 1.0412x; 1.0412x over previous
#include <cuda_runtime.h>
#include <cuda_fp16.h>

// Problem constants (fixed shapes)
#define NU 100000
#define NI 50000
#define NN 150000        // NU + NI
#define D  64
#define DE 16
#define NE 1500000
#define NP 14
#define EPS 1e-5f

#define NN2 (2 * NN)     // row counters for both layers
#define NE2 (2 * NE)     // CSR slots for both layers
#define SCAN_BLK 1024
#define NB2 ((NN2 + SCAN_BLK - 1) / SCAN_BLK)  // 293
#define ROWB ((NN + 7) / 8)                     // 18750 (8 warps/block)
#define HISTB ((NE2 / 4 + 255) / 256)           // 2930

// -------- scratch (device globals; no allocation allowed) --------
__device__ __half g_yh0[NN * D];    // LN features layer 0 (fp16)
__device__ __half g_yh1[NN * D];    // LN features layer 1 (fp16)
__device__ __half g_eh [NN * DE];   // eigs fp16
__device__ float  g_x0 [NN * D];    // layer-0 output (fp32 for final avg)
__device__ int    g_cnt[NN2];       // row degrees (both layers)
__device__ int    g_rs [NN2];       // block-local scan; bumped to local END by score
__device__ int2   g_csr[NE2];       // CSR: (c | pt<<20, e0 bits) — 8 B/slot
__device__ float  g_pwx[2 * NP];    // clip(exp(path_w),5) per layer
__device__ int    g_part[512];      // per-scan-block offsets (final, exclusive)
__device__ int    g_scan_ctr;

// ---------------------------------------------------------------
// K0: zero counters, reset scan counter, eigs -> fp16, pwx table.
// ---------------------------------------------------------------
__global__ void prep_kernel(const float* __restrict__ eigs,
                            const float* __restrict__ pw)
{
    int i = blockIdx.x * blockDim.x + threadIdx.x;
    if (i == 0) g_scan_ctr = 0;
    if (i < 2 * NP) g_pwx[i] = fminf(__expf(__ldg(pw + i)), 5.0f);
    if (i < NN2) g_cnt[i] = 0;
    if (i < NN * DE / 2) {
        float2 v = ((const float2*)eigs)[i];
        ((__half2*)g_eh)[i] = __floats2half2_rn(v.x, v.y);
    }
}

// ---------------------------------------------------------------
// K1: fused LN(layer 0) + histogram(both layers).
// g_cnt pre-zeroed in K0 (no in-kernel zeroing — R3's race).
// ---------------------------------------------------------------
__global__ void ln_hist_kernel(const float* __restrict__ ue,
                               const float* __restrict__ ie,
                               const int*   __restrict__ idx)
{
    if (blockIdx.x < ROWB) {
        int row = blockIdx.x * 8 + (threadIdx.x >> 5);
        if (row >= NN) return;
        int lane = threadIdx.x & 31;

        const float* p = (row < NU) ? (ue + (size_t)row * D)
                                    : (ie + (size_t)(row - NU) * D);
        float2 v = ((const float2*)p)[lane];

        float s = v.x + v.y;
        #pragma unroll
        for (int o = 16; o; o >>= 1) s += __shfl_xor_sync(0xffffffffu, s, o);
        float mu = s * (1.0f / D);

        float dx = v.x - mu, dy = v.y - mu;
        float vs = dx * dx + dy * dy;
        #pragma unroll
        for (int o = 16; o; o >>= 1) vs += __shfl_xor_sync(0xffffffffu, vs, o);
        float inv = rsqrtf(vs * (1.0f / D) + EPS);

        ((__half2*)(g_yh0 + (size_t)row * D))[lane] =
            __floats2half2_rn(dx * inv, dy * inv);
    } else {
        int e4 = (blockIdx.x - ROWB) * blockDim.x + threadIdx.x;
        if (e4 < NE2 / 4) {
            int layer = (e4 >= NE / 4);
            const int* rows = idx + (size_t)layer * 2 * NE;
            int4 r4 = ((const int4*)rows)[e4 - layer * (NE / 4)];
            int base = layer * NN;
            atomicAdd(&g_cnt[base + r4.x], 1);
            atomicAdd(&g_cnt[base + r4.y], 1);
            atomicAdd(&g_cnt[base + r4.z], 1);
            atomicAdd(&g_cnt[base + r4.w], 1);
        }
    }
}

// ---------------------------------------------------------------
// K2: block-local exclusive scan of g_cnt -> g_rs; last finishing
// block scans the block totals -> g_part (final offsets).
// ---------------------------------------------------------------
__device__ __forceinline__ int warp_incl_scan(int x, int lane)
{
    #pragma unroll
    for (int o = 1; o < 32; o <<= 1) {
        int t = __shfl_up_sync(0xffffffffu, x, o);
        if (lane >= o) x += t;
    }
    return x;
}

__global__ void scan_kernel()
{
    __shared__ int warpsum[32];
    __shared__ int s_total;
    __shared__ int s_isLast;

    int lane = threadIdx.x & 31;
    int wid  = threadIdx.x >> 5;
    int i = blockIdx.x * SCAN_BLK + threadIdx.x;
    int v = (i < NN2) ? g_cnt[i] : 0;

    int inc = warp_incl_scan(v, lane);
    if (lane == 31) warpsum[wid] = inc;
    __syncthreads();
    if (wid == 0) {
        int s  = warpsum[lane];
        int si = warp_incl_scan(s, lane);
        warpsum[lane] = si - s;
        if (lane == 31) s_total = si;
    }
    __syncthreads();
    int excl = inc - v + warpsum[wid];
    if (i < NN2) g_rs[i] = excl;                 // block-local exclusive scan

    if (threadIdx.x == 0) {
        g_part[blockIdx.x] = s_total;
        __threadfence();
        s_isLast = (atomicAdd(&g_scan_ctr, 1) == (int)gridDim.x - 1);
    }
    __syncthreads();

    if (s_isLast) {
        int pv = (threadIdx.x < NB2) ? g_part[threadIdx.x] : 0;
        int inc2 = warp_incl_scan(pv, lane);
        __syncthreads();
        if (lane == 31) warpsum[wid] = inc2;
        __syncthreads();
        if (wid == 0) {
            int s  = warpsum[lane];
            int si = warp_incl_scan(s, lane);
            warpsum[lane] = si - s;
        }
        __syncthreads();
        int excl2 = inc2 - pv + warpsum[wid];
        if (threadIdx.x < NB2) g_part[threadIdx.x] = excl2;
    }
}

// ---------------------------------------------------------------
// K3: scores in EDGE order, 8 lanes per FOUR edges + fused CSR
// scatter. One LDG.128 covers a full 128B feature row (minimum L1
// wavefronts). Edges processed in two staged pairs (A,B then C,D)
// to cap live registers; __launch_bounds__(256,8) pins occupancy.
// HFMA2 for both feature and eig dots.
// ---------------------------------------------------------------
__device__ __forceinline__ float dot16h(uint4 a, uint4 b)
{
    const __half2* ah = (const __half2*)&a;
    const __half2* bh = (const __half2*)&b;
    __half2 acc = __floats2half2_rn(0.f, 0.f);
    acc = __hfma2(ah[0], bh[0], acc);
    acc = __hfma2(ah[1], bh[1], acc);
    acc = __hfma2(ah[2], bh[2], acc);
    acc = __hfma2(ah[3], bh[3], acc);
    float2 f = __half22float2(acc);
    return f.x + f.y;
}

__global__ void __launch_bounds__(256, 8)
score_kernel(const __half* __restrict__ yh,
             const int*   __restrict__ rows,
             const int*   __restrict__ cols,
             const int*   __restrict__ pt,
             const float* __restrict__ lam,
             int rowBase)
{
    int t = blockIdx.x * blockDim.x + threadIdx.x;
    int grp = t >> 3;                  // edge-quad index
    if (grp >= NE / 4) return;
    int q = t & 7;

    int4 rr = __ldg((const int4*)rows + grp);   // rows[4g .. 4g+3]
    int4 cc = __ldg((const int4*)cols + grp);

    // ---- pair A,B: load (4 full-line loads + 4 eig loads), dot ----
    uint4 aA = __ldg((const uint4*)(yh + (size_t)rr.x * D) + q);
    uint4 bA = __ldg((const uint4*)(yh + (size_t)cc.x * D) + q);
    uint4 aB = __ldg((const uint4*)(yh + (size_t)rr.y * D) + q);
    uint4 bB = __ldg((const uint4*)(yh + (size_t)cc.y * D) + q);
    __half2 euA = __ldg((const __half2*)(g_eh + (size_t)rr.x * DE) + q);
    __half2 evA = __ldg((const __half2*)(g_eh + (size_t)cc.x * DE) + q);
    __half2 euB = __ldg((const __half2*)(g_eh + (size_t)rr.y * DE) + q);
    __half2 evB = __ldg((const __half2*)(g_eh + (size_t)cc.y * DE) + q);

    float dpA = dot16h(aA, bA);
    float dpB = dot16h(aB, bB);
    float2 eA2 = __half22float2(__hmul2(euA, evA));
    float2 eB2 = __half22float2(__hmul2(euB, evB));
    float ysA = eA2.x + eA2.y;
    float ysB = eB2.x + eB2.y;

    // ---- pair C,D ----
    uint4 aC = __ldg((const uint4*)(yh + (size_t)rr.z * D) + q);
    uint4 bC = __ldg((const uint4*)(yh + (size_t)cc.z * D) + q);
    uint4 aD = __ldg((const uint4*)(yh + (size_t)rr.w * D) + q);
    uint4 bD = __ldg((const uint4*)(yh + (size_t)cc.w * D) + q);
    __half2 euC = __ldg((const __half2*)(g_eh + (size_t)rr.z * DE) + q);
    __half2 evC = __ldg((const __half2*)(g_eh + (size_t)cc.z * DE) + q);
    __half2 euD = __ldg((const __half2*)(g_eh + (size_t)rr.w * DE) + q);
    __half2 evD = __ldg((const __half2*)(g_eh + (size_t)cc.w * DE) + q);

    float dpC = dot16h(aC, bC);
    float dpD = dot16h(aD, bD);
    float2 eC2 = __half22float2(__hmul2(euC, evC));
    float2 eD2 = __half22float2(__hmul2(euD, evD));
    float ysC = eC2.x + eC2.y;
    float ysD = eD2.x + eD2.y;

    float elam = __expf(__ldg(lam));
    float pA = dpA * 0.125f + elam * ysA;
    float pB = dpB * 0.125f + elam * ysB;
    float pC = dpC * 0.125f + elam * ysC;
    float pD = dpD * 0.125f + elam * ysD;
    #pragma unroll
    for (int o = 1; o <= 4; o <<= 1) {
        pA += __shfl_xor_sync(0xffffffffu, pA, o);
        pB += __shfl_xor_sync(0xffffffffu, pB, o);
        pC += __shfl_xor_sync(0xffffffffu, pC, o);
        pD += __shfl_xor_sync(0xffffffffu, pD, o);
    }

    // epilogue: lanes 0..3 handle edges A..D
    if (q < 4) {
        int4 pp = __ldg((const int4*)pt + grp);
        int   r, c, ptv; float p;
        if      (q == 0) { r = rr.x; c = cc.x; ptv = pp.x; p = pA; }
        else if (q == 1) { r = rr.y; c = cc.y; ptv = pp.y; p = pB; }
        else if (q == 2) { r = rr.z; c = cc.z; ptv = pp.z; p = pC; }
        else             { r = rr.w; c = cc.w; ptv = pp.w; p = pD; }
        float v0 = fminf(__expf(p), 5.0f);                     // clip(exp,-5,5)
        int ridx = rowBase + r;
        int pos = atomicAdd(&g_rs[ridx], 1) + __ldg(&g_part[ridx >> 10]);
        g_csr[pos] = make_int2(c | (ptv << 20), __float_as_int(v0));
    }
}

// ---------------------------------------------------------------
// K4: SpMM warp/row. CSR slots are 8B; main loop loads TWO slots per
// int4 (16B) instruction (peel one if row start is odd). e1 comes
// from the 14-entry pwx table (L1-resident broadcast). fp32 math.
//   MODE 0: epilogue LN -> yh1 fp16 + x0 fp32.
//   MODE 1: epilogue out = (emb + x0 + x)/3.
// ---------------------------------------------------------------
template<int MODE>
__global__ void spmm_kernel(const __half* __restrict__ yh,
                            int rowBase,
                            const float* __restrict__ pwx,   // &g_pwx[l*NP]
                            const float* __restrict__ ue,
                            const float* __restrict__ ie,
                            float* __restrict__ out)
{
    int row = blockIdx.x * 8 + (threadIdx.x >> 5);
    if (row >= NN) return;
    int lane = threadIdx.x & 31;

    int ridx = rowBase + row;
    int n  = g_cnt[ridx];
    // g_rs holds block-local END (bumped by score); add part, sub n.
    int st  = g_rs[ridx] + __ldg(&g_part[ridx >> 10]) - n;
    int end = st + n;

    float s0 = 0.f, s1 = 0.f;
    float a0x = 0.f, a0y = 0.f, a1x = 0.f, a1y = 0.f;

    int i = st;
    if ((i & 1) && i < end) {                    // peel to even index
        int2 cw = __ldg(&g_csr[i]);
        int   c   = cw.x & 0xFFFFF;
        float e1  = __ldg(pwx + (cw.x >> 20));
        float e0  = __int_as_float(cw.y);
        float2 v  = __half22float2(((const __half2*)(yh + (size_t)c * D))[lane]);
        a0x += e0 * v.x; a0y += e0 * v.y;
        a1x += e1 * v.x; a1y += e1 * v.y;
        s0 += e0; s1 += e1;
        i++;
    }
    for (; i + 2 <= end; i += 2) {
        int4 two = __ldg((const int4*)g_csr + (i >> 1));   // slots i, i+1
        int   cA  = two.x & 0xFFFFF;
        int   cB  = two.z & 0xFFFFF;
        float e1A = __ldg(pwx + (two.x >> 20));
        float e1B = __ldg(pwx + (two.z >> 20));
        float e0A = __int_as_float(two.y);
        float e0B = __int_as_float(two.w);
        __half2 hA = ((const __half2*)(yh + (size_t)cA * D))[lane];
        __half2 hB = ((const __half2*)(yh + (size_t)cB * D))[lane];
        float2 vA = __half22float2(hA);
        float2 vB = __half22float2(hB);
        a0x += e0A * vA.x + e0B * vB.x;
        a0y += e0A * vA.y + e0B * vB.y;
        a1x += e1A * vA.x + e1B * vB.x;
        a1y += e1A * vA.y + e1B * vB.y;
        s0 += e0A + e0B;
        s1 += e1A + e1B;
    }
    if (i < end) {
        int2 cw = __ldg(&g_csr[i]);
        int   c   = cw.x & 0xFFFFF;
        float e1  = __ldg(pwx + (cw.x >> 20));
        float e0  = __int_as_float(cw.y);
        float2 v  = __half22float2(((const __half2*)(yh + (size_t)c * D))[lane]);
        a0x += e0 * v.x; a0y += e0 * v.y;
        a1x += e1 * v.x; a1y += e1 * v.y;
        s0 += e0; s1 += e1;
    }

    float i0 = 0.5f / ((s0 == 0.f) ? 1.f : s0);
    float i1 = 0.5f / ((s1 == 0.f) ? 1.f : s1);
    float ax = a0x * i0 + a1x * i1;
    float ay = a0y * i0 + a1y * i1;

    if (MODE == 0) {
        // fused LayerNorm -> yh1 (fp16), plus x0 (fp32)
        float s = ax + ay;
        #pragma unroll
        for (int o = 16; o; o >>= 1) s += __shfl_xor_sync(0xffffffffu, s, o);
        float mu = s * (1.0f / D);
        float dx = ax - mu, dy = ay - mu;
        float vs = dx * dx + dy * dy;
        #pragma unroll
        for (int o = 16; o; o >>= 1) vs += __shfl_xor_sync(0xffffffffu, vs, o);
        float inv = rsqrtf(vs * (1.0f / D) + EPS);

        ((float2*)(g_x0 + (size_t)row * D))[lane] = make_float2(ax, ay);
        ((__half2*)(g_yh1 + (size_t)row * D))[lane] =
            __floats2half2_rn(dx * inv, dy * inv);
    } else {
        const float* emb = (row < NU) ? (ue + (size_t)row * D)
                                      : (ie + (size_t)(row - NU) * D);
        float2 e = ((const float2*)emb)[lane];
        float2 x = ((const float2*)(g_x0 + (size_t)row * D))[lane];
        const float t = 1.0f / 3.0f;
        ((float2*)(out + (size_t)row * D))[lane] =
            make_float2((e.x + x.x + ax) * t, (e.y + x.y + ay) * t);
    }
}

extern "C" void kernel_launch(void* const* d_in, const int* in_sizes, int n_in,
                              void* d_out, int out_size)
{
    const float* ue   = (const float*)d_in[0];  // [NU, D]
    const float* ie   = (const float*)d_in[1];  // [NI, D]
    const float* eigs = (const float*)d_in[2];  // [NN, DE]
    const float* lam  = (const float*)d_in[3];  // [2]
    const float* pw   = (const float*)d_in[4];  // [2, NP]
    const int*   idx  = (const int*)  d_in[5];  // [2, 2, NE]
    const int*   pt   = (const int*)  d_in[6];  // [2, NE]
    float* out = (float*)d_out;

    __half* yh0 = nullptr; __half* yh1 = nullptr; float* pwx = nullptr;
    cudaGetSymbolAddress((void**)&yh0, g_yh0);
    cudaGetSymbolAddress((void**)&yh1, g_yh1);
    cudaGetSymbolAddress((void**)&pwx, g_pwx);

    int prepT = NN * DE / 2;                     // 1.2M threads (covers NN2)
    prep_kernel   <<<(prepT + 255) / 256, 256>>>(eigs, pw);
    ln_hist_kernel<<<ROWB + HISTB, 256>>>(ue, ie, idx);
    scan_kernel   <<<NB2, SCAN_BLK>>>();

    int scoreB = ((NE / 4) * 8 + 255) / 256;
    // layer 0
    score_kernel  <<<scoreB, 256>>>(yh0, idx, idx + NE, pt, lam, 0);
    spmm_kernel<0><<<ROWB, 256>>>(yh0, 0, pwx, nullptr, nullptr, nullptr);
    // layer 1
    score_kernel  <<<scoreB, 256>>>(yh1, idx + 2 * NE, idx + 3 * NE,
                                    pt + NE, lam + 1, NN);
    spmm_kernel<1><<<ROWB, 256>>>(yh1, NN, pwx + NP, ue, ie, out);
}